// round 3
// baseline (speedup 1.0000x reference)
#include <cuda_runtime.h>
#include <math.h>

// features: [B=16, H=128, W=128, D=8, F=16] float32
// out[b,h,w,d,f] = flip_{W,D}( roll_{(5,-7),(H,W)}( rotate_40deg_NN(x) ) )
//
// Inverse chain per output element:
//   w1 = W-1-w ; d1 = D-1-d            (undo flip on W and D)
//   h2 = (h - 5) mod H ; w2 = (w1 + 7) mod W   (undo roll: rolled[i] = rot[i-shift])
//   (si,sj,valid) = NN inverse-rotation map at (h2,w2)
//   out = valid ? x[b, si, sj, d1, f] : 0
//
// Vectorized as float4 over F (F=16 -> 4 float4 per (b,h,w,d)).

#define B_ 16
#define H_ 128
#define W_ 128
#define D_ 8
#define F4_ 4           // F/4
#define N4_ (B_*H_*W_*D_*F4_)   // 8388608 float4 outputs

__global__ __launch_bounds__(256) void augment_kernel(
    const float4* __restrict__ in, float4* __restrict__ out,
    float c, float s)
{
    int idx = blockIdx.x * blockDim.x + threadIdx.x;
    if (idx >= N4_) return;

    // decompose: idx = (((b*H + h)*W + w)*D + d)*F4 + f4
    int f4 = idx & 3;
    int t  = idx >> 2;
    int d  = t & 7;   t >>= 3;
    int w  = t & 127; t >>= 7;
    int h  = t & 127;
    int b  = t >> 7;

    // undo flips
    int w1 = (W_ - 1) - w;
    int d1 = (D_ - 1) - d;
    // undo roll (shifts = (5, -7) on (H, W)): rolled[h][w] = rot[(h-5)%H][(w+7)%W]
    int h2 = h - 5;  if (h2 < 0)    h2 += H_;
    int w2 = w1 + 7; if (w2 >= W_)  w2 -= W_;

    // NN inverse rotation, center (63.5, 63.5), round-half-to-even like jnp.round
    float fi = (float)h2 - 63.5f;
    float fj = (float)w2 - 63.5f;
    float src_i =  c * fi + s * fj + 63.5f;
    float src_j = -s * fi + c * fj + 63.5f;
    int si = (int)rintf(src_i);
    int sj = (int)rintf(src_j);

    float4 v;
    if (si >= 0 && si < H_ && sj >= 0 && sj < W_) {
        int src = (((b * H_ + si) * W_ + sj) * D_ + d1) * F4_ + f4;
        v = in[src];
    } else {
        v = make_float4(0.f, 0.f, 0.f, 0.f);
    }
    out[idx] = v;
}

extern "C" void kernel_launch(void* const* d_in, const int* in_sizes, int n_in,
                              void* d_out, int out_size) {
    const float4* in = (const float4*)d_in[0];
    float4* out = (float4*)d_out;

    const double theta = 40.0 * 3.14159265358979323846 / 180.0;
    const float c = (float)cos(theta);
    const float s = (float)sin(theta);

    const int threads = 256;
    const int blocks = (N4_ + threads - 1) / threads;   // 32768
    augment_kernel<<<blocks, threads>>>(in, out, c, s);
}

// round 4
// speedup vs baseline: 1.0508x; 1.0508x over previous
#include <cuda_runtime.h>
#include <math.h>

// features: [B=16, H=128, W=128, D=8, F=16] float32
// out[b,h,w,d,f] = flip_{W,D}( roll_{(5,-7),(H,W)}( rotate_40deg_NN(x) ) )
//
// Inverse chain per output element:
//   w1 = W-1-w ; d1 = D-1-d                    (undo flips)
//   h2 = (h-5) mod H ; w2 = (w1+7) mod W       (undo roll)
//   (si,sj,valid) = NN inverse-rotation at (h2,w2)
//   out = valid ? x[b, si, sj, d1, f] : 0
//
// R3: grid-stride unroll x4, stride = N4/4 = exactly 4 batches.
// The spatial index (h,w,d,f4) is identical across the 4 chunks, so the
// rotation math is computed ONCE and the 4 gathers differ only by a constant
// batch offset. 4 independent LDG.128 + 4 independent STG.128 per thread
// (MLP=4) to cover DRAM latency; per-warp coalescing identical to R1.

#define B_ 16
#define H_ 128
#define W_ 128
#define D_ 8
#define F4_ 4                     // F/4
#define N4_ (B_*H_*W_*D_*F4_)     // 8388608 float4 outputs
#define UNROLL_ 4
#define STRIDE_ (N4_/UNROLL_)     // 2097152 float4 = 4 batches
#define BATCH4_ (H_*W_*D_*F4_)    // float4 per batch = 524288

__global__ __launch_bounds__(256) void augment_kernel(
    const float4* __restrict__ in, float4* __restrict__ out,
    float c, float s)
{
    int idx = blockIdx.x * blockDim.x + threadIdx.x;   // 0 .. STRIDE_-1

    // decompose: idx = (((b*H + h)*W + w)*D + d)*F4 + f4   (b in 0..3 here)
    int f4 = idx & 3;
    int t  = idx >> 2;
    int d  = t & 7;   t >>= 3;
    int w  = t & 127; t >>= 7;
    int h  = t & 127;
    int b  = t >> 7;

    // undo flips
    int w1 = (W_ - 1) - w;
    int d1 = (D_ - 1) - d;
    // undo roll (shifts = (5, -7) on (H, W))
    int h2 = h - 5;  if (h2 < 0)    h2 += H_;
    int w2 = w1 + 7; if (w2 >= W_)  w2 -= W_;

    // NN inverse rotation, center 63.5, round-half-to-even (jnp.round)
    float fi = (float)h2 - 63.5f;
    float fj = (float)w2 - 63.5f;
    float src_i =  c * fi + s * fj + 63.5f;
    float src_j = -s * fi + c * fj + 63.5f;
    int si = (int)rintf(src_i);
    int sj = (int)rintf(src_j);

    bool valid = (si >= 0) & (si < H_) & (sj >= 0) & (sj < W_);

    float4 v[UNROLL_];
    if (valid) {
        int src = (((b * H_ + si) * W_ + sj) * D_ + d1) * F4_ + f4;
        #pragma unroll
        for (int k = 0; k < UNROLL_; k++)
            v[k] = in[src + k * (4 * BATCH4_)];
    } else {
        #pragma unroll
        for (int k = 0; k < UNROLL_; k++)
            v[k] = make_float4(0.f, 0.f, 0.f, 0.f);
    }

    #pragma unroll
    for (int k = 0; k < UNROLL_; k++)
        out[idx + k * STRIDE_] = v[k];
}

extern "C" void kernel_launch(void* const* d_in, const int* in_sizes, int n_in,
                              void* d_out, int out_size) {
    const float4* in = (const float4*)d_in[0];
    float4* out = (float4*)d_out;

    const double theta = 40.0 * 3.14159265358979323846 / 180.0;
    const float c = (float)cos(theta);
    const float s = (float)sin(theta);

    const int threads = 256;
    const int blocks = STRIDE_ / threads;   // 8192
    augment_kernel<<<blocks, threads>>>(in, out, c, s);
}

// round 5
// speedup vs baseline: 1.0568x; 1.0057x over previous
#include <cuda_runtime.h>
#include <math.h>

// features: [B=16, H=128, W=128, D=8, F=16] float32
// out[b,h,w,d,f] = flip_{W,D}( roll_{(5,-7),(H,W)}( rotate_40deg_NN(x) ) )
//
// Inverse chain per output element:
//   w1 = W-1-w ; d1 = D-1-d                    (undo flips)
//   h2 = (h-5) mod H ; w2 = (w1+7) mod W       (undo roll)
//   (si,sj,valid) = NN inverse-rotation at (h2,w2)
//   out = valid ? x[b, si, sj, d1, f] : 0
//
// R3: grid-stride unroll x4, stride = N4/4 = exactly 4 batches.
// The spatial index (h,w,d,f4) is identical across the 4 chunks, so the
// rotation math is computed ONCE and the 4 gathers differ only by a constant
// batch offset. 4 independent LDG.128 + 4 independent STG.128 per thread
// (MLP=4) to cover DRAM latency; per-warp coalescing identical to R1.

#define B_ 16
#define H_ 128
#define W_ 128
#define D_ 8
#define F4_ 4                     // F/4
#define N4_ (B_*H_*W_*D_*F4_)     // 8388608 float4 outputs
#define UNROLL_ 4
#define STRIDE_ (N4_/UNROLL_)     // 2097152 float4 = 4 batches
#define BATCH4_ (H_*W_*D_*F4_)    // float4 per batch = 524288

__global__ __launch_bounds__(256) void augment_kernel(
    const float4* __restrict__ in, float4* __restrict__ out,
    float c, float s)
{
    int idx = blockIdx.x * blockDim.x + threadIdx.x;   // 0 .. STRIDE_-1

    // decompose: idx = (((b*H + h)*W + w)*D + d)*F4 + f4   (b in 0..3 here)
    int f4 = idx & 3;
    int t  = idx >> 2;
    int d  = t & 7;   t >>= 3;
    int w  = t & 127; t >>= 7;
    int h  = t & 127;
    int b  = t >> 7;

    // undo flips
    int w1 = (W_ - 1) - w;
    int d1 = (D_ - 1) - d;
    // undo roll (shifts = (5, -7) on (H, W))
    int h2 = h - 5;  if (h2 < 0)    h2 += H_;
    int w2 = w1 + 7; if (w2 >= W_)  w2 -= W_;

    // NN inverse rotation, center 63.5, round-half-to-even (jnp.round)
    float fi = (float)h2 - 63.5f;
    float fj = (float)w2 - 63.5f;
    float src_i =  c * fi + s * fj + 63.5f;
    float src_j = -s * fi + c * fj + 63.5f;
    int si = (int)rintf(src_i);
    int sj = (int)rintf(src_j);

    bool valid = (si >= 0) & (si < H_) & (sj >= 0) & (sj < W_);

    float4 v[UNROLL_];
    if (valid) {
        int src = (((b * H_ + si) * W_ + sj) * D_ + d1) * F4_ + f4;
        #pragma unroll
        for (int k = 0; k < UNROLL_; k++)
            v[k] = in[src + k * (4 * BATCH4_)];
    } else {
        #pragma unroll
        for (int k = 0; k < UNROLL_; k++)
            v[k] = make_float4(0.f, 0.f, 0.f, 0.f);
    }

    #pragma unroll
    for (int k = 0; k < UNROLL_; k++)
        out[idx + k * STRIDE_] = v[k];
}

extern "C" void kernel_launch(void* const* d_in, const int* in_sizes, int n_in,
                              void* d_out, int out_size) {
    const float4* in = (const float4*)d_in[0];
    float4* out = (float4*)d_out;

    const double theta = 40.0 * 3.14159265358979323846 / 180.0;
    const float c = (float)cos(theta);
    const float s = (float)sin(theta);

    const int threads = 256;
    const int blocks = STRIDE_ / threads;   // 8192
    augment_kernel<<<blocks, threads>>>(in, out, c, s);
}

// round 6
// speedup vs baseline: 1.0672x; 1.0098x over previous
#include <cuda_runtime.h>
#include <math.h>

// features: [B=16, H=128, W=128, D=8, F=16] float32
// out[b,h,w,d,f] = flip_{W,D}( roll_{(5,-7),(H,W)}( rotate_40deg_NN(x) ) )
//
// Inverse chain per output element:
//   w1 = W-1-w ; d1 = D-1-d                    (undo flips)
//   h2 = (h-5) mod H ; w2 = (w1+7) mod W       (undo roll)
//   (si,sj,valid) = NN inverse-rotation at (h2,w2)
//   out = valid ? x[b, si, sj, d1, f] : 0
//
// R5: unroll x8 across batches (stride = N4/8 = exactly 2 batches), rotation
// math computed once per thread; 8 independent LDG.128 (MLP=8) + 8 STG.128.
// Stores use __stcs (evict-first streaming) so the never-re-read output
// stream does not evict the NN-gather read set from L2.

#define B_ 16
#define H_ 128
#define W_ 128
#define D_ 8
#define F4_ 4                     // F/4
#define N4_ (B_*H_*W_*D_*F4_)     // 8388608 float4 outputs
#define UNROLL_ 8
#define STRIDE_ (N4_/UNROLL_)     // 1048576 float4 = 2 batches
#define BATCH4_ (H_*W_*D_*F4_)    // float4 per batch = 524288

__global__ __launch_bounds__(256) void augment_kernel(
    const float4* __restrict__ in, float4* __restrict__ out,
    float c, float s)
{
    int idx = blockIdx.x * blockDim.x + threadIdx.x;   // 0 .. STRIDE_-1

    // decompose: idx = (((b*H + h)*W + w)*D + d)*F4 + f4   (b in 0..1 here)
    int f4 = idx & 3;
    int t  = idx >> 2;
    int d  = t & 7;   t >>= 3;
    int w  = t & 127; t >>= 7;
    int h  = t & 127;
    int b  = t >> 7;

    // undo flips
    int w1 = (W_ - 1) - w;
    int d1 = (D_ - 1) - d;
    // undo roll (shifts = (5, -7) on (H, W))
    int h2 = h - 5;  if (h2 < 0)    h2 += H_;
    int w2 = w1 + 7; if (w2 >= W_)  w2 -= W_;

    // NN inverse rotation, center 63.5, round-half-to-even (jnp.round)
    float fi = (float)h2 - 63.5f;
    float fj = (float)w2 - 63.5f;
    float src_i =  c * fi + s * fj + 63.5f;
    float src_j = -s * fi + c * fj + 63.5f;
    int si = (int)rintf(src_i);
    int sj = (int)rintf(src_j);

    bool valid = (si >= 0) & (si < H_) & (sj >= 0) & (sj < W_);

    float4 v[UNROLL_];
    if (valid) {
        int src = (((b * H_ + si) * W_ + sj) * D_ + d1) * F4_ + f4;
        #pragma unroll
        for (int k = 0; k < UNROLL_; k++)
            v[k] = in[src + k * (2 * BATCH4_)];
    } else {
        #pragma unroll
        for (int k = 0; k < UNROLL_; k++)
            v[k] = make_float4(0.f, 0.f, 0.f, 0.f);
    }

    #pragma unroll
    for (int k = 0; k < UNROLL_; k++)
        __stcs(&out[idx + k * STRIDE_], v[k]);
}

extern "C" void kernel_launch(void* const* d_in, const int* in_sizes, int n_in,
                              void* d_out, int out_size) {
    const float4* in = (const float4*)d_in[0];
    float4* out = (float4*)d_out;

    const double theta = 40.0 * 3.14159265358979323846 / 180.0;
    const float c = (float)cos(theta);
    const float s = (float)sin(theta);

    const int threads = 256;
    const int blocks = STRIDE_ / threads;   // 4096
    augment_kernel<<<blocks, threads>>>(in, out, c, s);
}